// round 11
// baseline (speedup 1.0000x reference)
#include <cuda_runtime.h>
#include <cuda_fp16.h>
#include <math_constants.h>
#include <stdint.h>

// Problem constants
#define B_   2
#define T_   2048
#define D_   2048
#define H_   16
#define HKV_ 4
#define HD_  128
#define G_   (H_ / HKV_)      // 4
#define M_   (B_ * T_)        // 4096
#define KVD_ (HKV_ * HD_)     // 512

// ---------------------------------------------------------------------------
// Scratch (device globals; no allocation allowed) — all fp16
// ---------------------------------------------------------------------------
__device__ __half g_xh[(size_t)M_ * D_];     // 16 MB
__device__ __half g_wqh[(size_t)D_ * D_];    //  8 MB
__device__ __half g_wkh[(size_t)KVD_ * D_];  //  2 MB
__device__ __half g_wvh[(size_t)KVD_ * D_];  //  2 MB
__device__ __half g_woh[(size_t)D_ * D_];    //  8 MB
__device__ __half g_q[(size_t)M_ * D_];      // 16 MB
__device__ __half g_k[(size_t)M_ * KVD_];    //  4 MB
__device__ __half g_v[(size_t)M_ * KVD_];    //  4 MB
__device__ __half g_attn[(size_t)M_ * D_];   // 16 MB

// ---------------------------------------------------------------------------
// Helpers
// ---------------------------------------------------------------------------
__device__ __forceinline__ uint32_t pk_h2(float lo, float hi) {
    half2 h = __floats2half2_rn(lo, hi);
    return *(uint32_t*)&h;
}

__device__ __forceinline__ uint32_t smem_u32(const void* p) {
    uint32_t a;
    asm("{ .reg .u64 t; cvta.to.shared.u64 t, %1; cvt.u32.u64 %0, t; }"
        : "=r"(a) : "l"(p));
    return a;
}

#define MMA_F16(c, a, b)                                                      \
    asm volatile(                                                             \
        "mma.sync.aligned.m16n8k16.row.col.f32.f16.f16.f32 "                  \
        "{%0,%1,%2,%3},{%4,%5,%6,%7},{%8,%9},{%0,%1,%2,%3};"                  \
        : "+f"((c)[0]), "+f"((c)[1]), "+f"((c)[2]), "+f"((c)[3])              \
        : "r"((a)[0]), "r"((a)[1]), "r"((a)[2]), "r"((a)[3]),                 \
          "r"((b)[0]), "r"((b)[1]))

#define LDSM_X4(r0, r1, r2, r3, addr)                                         \
    asm volatile(                                                             \
        "ldmatrix.sync.aligned.m8n8.x4.shared.b16 {%0,%1,%2,%3}, [%4];"       \
        : "=r"(r0), "=r"(r1), "=r"(r2), "=r"(r3) : "r"(addr))

#define LDSM_X4_T(r0, r1, r2, r3, addr)                                       \
    asm volatile(                                                             \
        "ldmatrix.sync.aligned.m8n8.x4.trans.shared.b16 {%0,%1,%2,%3}, [%4];" \
        : "=r"(r0), "=r"(r1), "=r"(r2), "=r"(r3) : "r"(addr))

#define CP_ASYNC16(dst, src)                                                  \
    asm volatile("cp.async.cg.shared.global [%0], [%1], 16;"                  \
                 :: "r"(dst), "l"(src))
#define CP_COMMIT() asm volatile("cp.async.commit_group;" ::: "memory")
#define CP_WAIT0()  asm volatile("cp.async.wait_group 0;" ::: "memory")
#define CP_WAIT1()  asm volatile("cp.async.wait_group 1;" ::: "memory")

// ---------------------------------------------------------------------------
// fp32 -> fp16 conversion (8 floats / thread)
// ---------------------------------------------------------------------------
__global__ __launch_bounds__(256) void f2h_kernel(
    const float* __restrict__ in, __half* __restrict__ out, int n)
{
    int i = (blockIdx.x * 256 + threadIdx.x) * 8;
    if (i >= n) return;
    float4 a = *(const float4*)(in + i);
    float4 b = *(const float4*)(in + i + 4);
    uint4 o = { pk_h2(a.x, a.y), pk_h2(a.z, a.w),
                pk_h2(b.x, b.y), pk_h2(b.z, b.w) };
    *(uint4*)(out + i) = o;
}

// ---------------------------------------------------------------------------
// fp16 tensor-core GEMM, 3-stage cp.async pipeline.
// C[M,N] = A[M,K] @ Bm[N,K]^T; BM=BN=128, BK=32, 256 threads, warp tile 64x32.
// Smem row stride 20 words; 3 buffers each for A and B (wait_group 1 gives
// every copy two iterations of slack). Half or float output.
// ---------------------------------------------------------------------------
#define HSTRIDE 20
#define HROW_BYTES (HSTRIDE * 4)                 // 80
#define HTILE_WORDS (128 * HSTRIDE)              // 2560 u32 per tile
#define HTILE_BYTES (HTILE_WORDS * 4)            // 10240
#define GEMM_SMEM_BYTES (6 * HTILE_BYTES)        // 61440 B

__global__ __launch_bounds__(256) void gemm_nt_h_kernel(
    const __half* __restrict__ A, const __half* __restrict__ Bm,
    __half* __restrict__ Ch, float* __restrict__ Cf, int M, int N, int K)
{
    extern __shared__ uint32_t smw[];
    const uint32_t smBase = smem_u32(smw);

    const int tid  = threadIdx.x;
    const int lane = tid & 31;
    const int warp = tid >> 5;
    const int row0 = blockIdx.y * 128;
    const int col0 = blockIdx.x * 128;
    const int wm   = (warp >> 2) * 64;
    const int wn   = (warp & 3) * 32;
    const int lk   = lane & 3;
    const int lr   = lane >> 2;

    const uint32_t aoff = (uint32_t)(lane & 15) * HROW_BYTES + (uint32_t)(lane >> 4) * 16;
    const uint32_t boff = ((uint32_t)((lane >> 4) * 8 + (lane & 7))) * HROW_BYTES
                        + (uint32_t)((lane >> 3) & 1) * 16;

    // global-load coords: idx -> m = idx>>2, half col = (idx&3)*8
    int mL[2], hcL[2];
    uint32_t stA[2], stB[2];
#pragma unroll
    for (int t = 0; t < 2; t++) {
        int idx = tid + 256 * t;
        mL[t]  = idx >> 2;
        hcL[t] = (idx & 3) << 3;
        uint32_t wb = (uint32_t)(mL[t] * HSTRIDE + ((idx & 3) << 2)) * 4;
        stA[t] = smBase + wb;                          // A buffers at 0,1,2
        stB[t] = smBase + 3 * HTILE_BYTES + wb;        // B buffers at 3,4,5
    }

    float c[4][4][4];
#pragma unroll
    for (int mi = 0; mi < 4; mi++)
#pragma unroll
        for (int ni = 0; ni < 4; ni++)
#pragma unroll
            for (int r = 0; r < 4; r++) c[mi][ni][r] = 0.f;

    const int niter = K >> 5;

    // prologue: stages 0 and 1
#pragma unroll
    for (int st = 0; st < 2; st++) {
        const int k0 = st << 5;
        const uint32_t bo = (uint32_t)st * HTILE_BYTES;
#pragma unroll
        for (int t = 0; t < 2; t++) {
            CP_ASYNC16(stA[t] + bo, &A [(size_t)(row0 + mL[t]) * K + k0 + hcL[t]]);
            CP_ASYNC16(stB[t] + bo, &Bm[(size_t)(col0 + mL[t]) * K + k0 + hcL[t]]);
        }
        CP_COMMIT();
    }

    int buf = 0;                 // buffer index of iteration `it`
    for (int it = 0; it < niter; ++it) {
        CP_WAIT1();              // stage `it` resident (≤1 group pending)
        __syncthreads();

        // prefetch stage it+2 into buffer (it+2)%3 (last read in it-1: WAR-safe)
        if (it + 2 < niter) {
            int nb = buf + 2; if (nb >= 3) nb -= 3;
            const int k0 = (it + 2) << 5;
            const uint32_t bo = (uint32_t)nb * HTILE_BYTES;
#pragma unroll
            for (int t = 0; t < 2; t++) {
                CP_ASYNC16(stA[t] + bo, &A [(size_t)(row0 + mL[t]) * K + k0 + hcL[t]]);
                CP_ASYNC16(stB[t] + bo, &Bm[(size_t)(col0 + mL[t]) * K + k0 + hcL[t]]);
            }
            CP_COMMIT();
        }

        const uint32_t aB = smBase + (uint32_t)buf * HTILE_BYTES + aoff;
        const uint32_t bB = smBase + (uint32_t)(3 + buf) * HTILE_BYTES + boff;
#pragma unroll
        for (int s = 0; s < 2; s++) {
            const uint32_t so = (uint32_t)s * 32;
            uint32_t af[4][4], bf[4][2];
#pragma unroll
            for (int mi = 0; mi < 4; mi++)
                LDSM_X4(af[mi][0], af[mi][1], af[mi][2], af[mi][3],
                        aB + (uint32_t)(wm + 16 * mi) * HROW_BYTES + so);
#pragma unroll
            for (int p = 0; p < 2; p++)
                LDSM_X4(bf[2 * p][0], bf[2 * p][1], bf[2 * p + 1][0], bf[2 * p + 1][1],
                        bB + (uint32_t)(wn + 16 * p) * HROW_BYTES + so);
#pragma unroll
            for (int mi = 0; mi < 4; mi++)
#pragma unroll
                for (int ni = 0; ni < 4; ni++)
                    MMA_F16(c[mi][ni], af[mi], bf[ni]);
        }
        __syncthreads();
        if (++buf == 3) buf = 0;
    }

#pragma unroll
    for (int mi = 0; mi < 4; mi++) {
#pragma unroll
        for (int ni = 0; ni < 4; ni++) {
            int r  = row0 + wm + 16 * mi + lr;
            int cc = col0 + wn + 8 * ni + 2 * lk;
            if (Ch) {
                *(uint32_t*)&Ch[(size_t)r * N + cc]       = pk_h2(c[mi][ni][0], c[mi][ni][1]);
                *(uint32_t*)&Ch[(size_t)(r + 8) * N + cc] = pk_h2(c[mi][ni][2], c[mi][ni][3]);
            } else {
                Cf[(size_t)r * N + cc]           = c[mi][ni][0];
                Cf[(size_t)r * N + cc + 1]       = c[mi][ni][1];
                Cf[(size_t)(r + 8) * N + cc]     = c[mi][ni][2];
                Cf[(size_t)(r + 8) * N + cc + 1] = c[mi][ni][3];
            }
        }
    }
}

// ---------------------------------------------------------------------------
// RoPE on half buffers; folds 1/sqrt(HD) scale into Q.
// ---------------------------------------------------------------------------
__global__ __launch_bounds__(256) void rope_h_kernel(
    __half* __restrict__ q, __half* __restrict__ k,
    const float* __restrict__ cosT, const float* __restrict__ sinT)
{
    const int bt  = blockIdx.x;
    const int t   = bt & (T_ - 1);
    const int tid = threadIdx.x;
    const float scale = 0.08838834764831845f;
    const float* cr = cosT + (size_t)t * HD_;
    const float* sr = sinT + (size_t)t * HD_;

    __half* qrow = q + (size_t)bt * D_;
    for (int p = tid; p < H_ * 64; p += 256) {
        int h = p >> 6, i = p & 63;
        __half* base = qrow + h * HD_;
        float q1 = __half2float(base[i]), q2 = __half2float(base[i + 64]);
        base[i]      = __float2half_rn((q1 * cr[i]      - q2 * sr[i]) * scale);
        base[i + 64] = __float2half_rn((q2 * cr[i + 64] + q1 * sr[i + 64]) * scale);
    }
    __half* krow = k + (size_t)bt * KVD_;
    for (int p = tid; p < HKV_ * 64; p += 256) {
        int h = p >> 6, i = p & 63;
        __half* base = krow + h * HD_;
        float k1 = __half2float(base[i]), k2 = __half2float(base[i + 64]);
        base[i]      = __float2half_rn(k1 * cr[i]      - k2 * sr[i]);
        base[i + 64] = __float2half_rn(k2 * cr[i + 64] + k1 * sr[i + 64]);
    }
}

// ---------------------------------------------------------------------------
// fp16 flash attention, cp.async double-buffered K/V.
// Grid: (T/128, H, B); qt REVERSED (heaviest CTAs first — LPT scheduling).
// Block: 256 = 8 warps; warp w owns q-rows [w*16,w*16+16).
// Smem: two buffers of { Ks[64][68], Vs[64][68] } u32 words.
// ---------------------------------------------------------------------------
#define AT_BUF_WORDS 8704                 // Ks + Vs per buffer
#define AT_BUF_BYTES (AT_BUF_WORDS * 4)   // 34816
#define AT_VS_WOFF   4352
#define ATTN_SMEM_BYTES (2 * AT_BUF_BYTES)   // 69632
#define KS_ROW_BYTES 272                  // 68 words

__global__ __launch_bounds__(256) void attn_f16_kernel(
    const __half* __restrict__ q, const __half* __restrict__ k,
    const __half* __restrict__ v, __half* __restrict__ o)
{
    extern __shared__ uint32_t sw[];
    uint32_t* Qs = sw;                 // staging [128][68], aliases both buffers

    const int qt  = (int)(gridDim.x - 1 - blockIdx.x);   // heavy tiles first
    const int h   = blockIdx.y;
    const int b   = blockIdx.z;
    const int kvh = h >> 2;
    const int q0  = qt * 128;
    const int tid  = threadIdx.x;
    const int lane = tid & 31;
    const int w    = tid >> 5;
    const int lr   = lane >> 2;
    const int lk   = lane & 3;

    const uint32_t smB = smem_u32(sw);
    const uint32_t brow   = (uint32_t)((lane >> 4) * 8 + (lane & 7));
    const uint32_t bcol16 = (uint32_t)((lane >> 3) & 1) * 16;
    const uint32_t arow   = (uint32_t)(lane & 15);
    const uint32_t asel16 = (uint32_t)(lane >> 4) * 16;

    // per-thread K/V load coords
    const int krow  = tid >> 2;                 // key 0..63
    const int kd0   = (tid & 3) * 32;           // halves
    const uint32_t kvw = (uint32_t)(krow * 68 + (kd0 >> 1)) * 4;

    // ---- stage Q (half, scale pre-folded) and pull A-fragments ----
    {
        int row = tid >> 1;
        int d0  = (tid & 1) * 64;
        const __half* src = q + (size_t)(b * T_ + q0 + row) * D_ + h * HD_ + d0;
#pragma unroll
        for (int j = 0; j < 64; j += 8)
            *(uint4*)&Qs[row * 68 + ((d0 + j) >> 1)] = *(const uint4*)(src + j);
    }
    __syncthreads();

    uint32_t aQ[8][4];
#pragma unroll
    for (int c = 0; c < 8; c++)
        LDSM_X4(aQ[c][0], aQ[c][1], aQ[c][2], aQ[c][3],
                smB + (uint32_t)(w * 16 + arow) * KS_ROW_BYTES
                    + (uint32_t)c * 32 + asel16);
    __syncthreads();

    float O[16][4];
#pragma unroll
    for (int nt = 0; nt < 16; nt++)
#pragma unroll
        for (int r = 0; r < 4; r++) O[nt][r] = 0.f;
    float m0 = -CUDART_INF_F, m1 = -CUDART_INF_F, l0 = 0.f, l1 = 0.f;

    const int row0g = q0 + w * 16 + lr;
    const int nkt = 2 * qt + 2;

    const __half* kbase = k + (size_t)(b * T_) * KVD_ + kvh * HD_ + kd0 + (size_t)krow * KVD_;
    const __half* vbase = v + (size_t)(b * T_) * KVD_ + kvh * HD_ + kd0 + (size_t)krow * KVD_;

    // prologue: async-load tile 0 into buffer 0
#pragma unroll
    for (int j = 0; j < 4; j++) {
        CP_ASYNC16(smB + kvw + 16u * j,                    kbase + 8 * j);
        CP_ASYNC16(smB + AT_VS_WOFF * 4 + kvw + 16u * j,   vbase + 8 * j);
    }
    CP_COMMIT();
    CP_WAIT0();
    __syncthreads();

    for (int kt = 0; kt < nkt; kt++) {
        const uint32_t bufB = smB + (uint32_t)(kt & 1) * AT_BUF_BYTES;

        if (kt + 1 < nkt) {
            const uint32_t nb = smB + (uint32_t)((kt + 1) & 1) * AT_BUF_BYTES;
            const size_t goff = (size_t)(kt + 1) * 64 * KVD_;
#pragma unroll
            for (int j = 0; j < 4; j++) {
                CP_ASYNC16(nb + kvw + 16u * j,                  kbase + goff + 8 * j);
                CP_ASYNC16(nb + AT_VS_WOFF * 4 + kvw + 16u * j, vbase + goff + 8 * j);
            }
            CP_COMMIT();
        }

        const int k0 = kt * 64;
        const bool active = (k0 <= q0 + w * 16 + 15);   // warp-uniform
        if (active) {
            const uint32_t KsB = bufB;
            const uint32_t VsB = bufB + AT_VS_WOFF * 4;

            // ---- S = Q K^T ----
            float s[8][4];
#pragma unroll
            for (int nt = 0; nt < 8; nt++)
#pragma unroll
                for (int r = 0; r < 4; r++) s[nt][r] = 0.f;

#pragma unroll
            for (int c = 0; c < 8; c++) {
                uint32_t bf[8][2];
#pragma unroll
                for (int p = 0; p < 4; p++)
                    LDSM_X4(bf[2 * p][0], bf[2 * p][1], bf[2 * p + 1][0], bf[2 * p + 1][1],
                            KsB + (uint32_t)(p * 16 + brow) * KS_ROW_BYTES
                                + (uint32_t)c * 32 + bcol16);
#pragma unroll
                for (int nt = 0; nt < 8; nt++)
                    MMA_F16(s[nt], aQ[c], bf[nt]);
            }

            // ---- causal mask ----
            if (k0 + 63 > q0 + w * 16) {
#pragma unroll
                for (int nt = 0; nt < 8; nt++) {
                    int c0 = k0 + nt * 8 + 2 * lk;
                    if (c0     > row0g)     s[nt][0] = -CUDART_INF_F;
                    if (c0 + 1 > row0g)     s[nt][1] = -CUDART_INF_F;
                    if (c0     > row0g + 8) s[nt][2] = -CUDART_INF_F;
                    if (c0 + 1 > row0g + 8) s[nt][3] = -CUDART_INF_F;
                }
            }

            // ---- online softmax ----
            float mt0 = -CUDART_INF_F, mt1 = -CUDART_INF_F;
#pragma unroll
            for (int nt = 0; nt < 8; nt++) {
                mt0 = fmaxf(mt0, fmaxf(s[nt][0], s[nt][1]));
                mt1 = fmaxf(mt1, fmaxf(s[nt][2], s[nt][3]));
            }
#pragma unroll
            for (int off = 1; off <= 2; off <<= 1) {
                mt0 = fmaxf(mt0, __shfl_xor_sync(0xffffffffu, mt0, off));
                mt1 = fmaxf(mt1, __shfl_xor_sync(0xffffffffu, mt1, off));
            }
            float mn0 = fmaxf(m0, mt0), mn1 = fmaxf(m1, mt1);
            float al0 = __expf(m0 - mn0), al1 = __expf(m1 - mn1);
            m0 = mn0; m1 = mn1;

            float sum0 = 0.f, sum1 = 0.f;
#pragma unroll
            for (int nt = 0; nt < 8; nt++) {
                s[nt][0] = __expf(s[nt][0] - mn0); sum0 += s[nt][0];
                s[nt][1] = __expf(s[nt][1] - mn0); sum0 += s[nt][1];
                s[nt][2] = __expf(s[nt][2] - mn1); sum1 += s[nt][2];
                s[nt][3] = __expf(s[nt][3] - mn1); sum1 += s[nt][3];
            }
#pragma unroll
            for (int off = 1; off <= 2; off <<= 1) {
                sum0 += __shfl_xor_sync(0xffffffffu, sum0, off);
                sum1 += __shfl_xor_sync(0xffffffffu, sum1, off);
            }
            l0 = l0 * al0 + sum0;
            l1 = l1 * al1 + sum1;
#pragma unroll
            for (int nt = 0; nt < 16; nt++) {
                O[nt][0] *= al0; O[nt][1] *= al0;
                O[nt][2] *= al1; O[nt][3] *= al1;
            }

            // ---- O += P V  (P in registers; V frags via ldmatrix.trans) ----
#pragma unroll
            for (int c = 0; c < 4; c++) {
                uint32_t pa[4];
                pa[0] = pk_h2(s[2 * c][0],     s[2 * c][1]);
                pa[1] = pk_h2(s[2 * c][2],     s[2 * c][3]);
                pa[2] = pk_h2(s[2 * c + 1][0], s[2 * c + 1][1]);
                pa[3] = pk_h2(s[2 * c + 1][2], s[2 * c + 1][3]);
#pragma unroll
                for (int p = 0; p < 8; p++) {
                    uint32_t vb[2][2];
                    LDSM_X4_T(vb[0][0], vb[0][1], vb[1][0], vb[1][1],
                              VsB + (uint32_t)(c * 16 + arow) * KS_ROW_BYTES
                                  + (uint32_t)p * 32 + asel16);
                    MMA_F16(O[2 * p],     pa, vb[0]);
                    MMA_F16(O[2 * p + 1], pa, vb[1]);
                }
            }
        }

        if (kt + 1 < nkt) CP_WAIT0();
        __syncthreads();
    }

    // ---- epilogue (half out) ----
    float inv0 = 1.0f / l0, inv1 = 1.0f / l1;
    size_t r0base = (size_t)(b * T_ + q0 + w * 16 + lr) * D_ + h * HD_;
    size_t r1base = (size_t)(b * T_ + q0 + w * 16 + lr + 8) * D_ + h * HD_;
#pragma unroll
    for (int nt = 0; nt < 16; nt++) {
        *(uint32_t*)&o[r0base + nt * 8 + 2 * lk] = pk_h2(O[nt][0] * inv0, O[nt][1] * inv0);
        *(uint32_t*)&o[r1base + nt * 8 + 2 * lk] = pk_h2(O[nt][2] * inv1, O[nt][3] * inv1);
    }
}

// ---------------------------------------------------------------------------
// Launcher
// ---------------------------------------------------------------------------
extern "C" void kernel_launch(void* const* d_in, const int* in_sizes, int n_in,
                              void* d_out, int out_size)
{
    const float* x    = (const float*)d_in[0];
    const float* cosT = (const float*)d_in[1];
    const float* sinT = (const float*)d_in[2];
    const float* Wq   = (const float*)d_in[3];
    const float* Wk   = (const float*)d_in[4];
    const float* Wv   = (const float*)d_in[5];
    const float* Wo   = (const float*)d_in[6];
    float* out = (float*)d_out;

    __half *xh, *wqh, *wkh, *wvh, *woh, *gq, *gk, *gv, *gattn;
    cudaGetSymbolAddress((void**)&xh,    g_xh);
    cudaGetSymbolAddress((void**)&wqh,   g_wqh);
    cudaGetSymbolAddress((void**)&wkh,   g_wkh);
    cudaGetSymbolAddress((void**)&wvh,   g_wvh);
    cudaGetSymbolAddress((void**)&woh,   g_woh);
    cudaGetSymbolAddress((void**)&gq,    g_q);
    cudaGetSymbolAddress((void**)&gk,    g_k);
    cudaGetSymbolAddress((void**)&gv,    g_v);
    cudaGetSymbolAddress((void**)&gattn, g_attn);

    cudaFuncSetAttribute(attn_f16_kernel, cudaFuncAttributeMaxDynamicSharedMemorySize,
                         ATTN_SMEM_BYTES);
    cudaFuncSetAttribute(gemm_nt_h_kernel,
                         cudaFuncAttributeMaxDynamicSharedMemorySize,
                         GEMM_SMEM_BYTES);

    dim3 blk(256);
    f2h_kernel<<<M_ * D_ / 2048,   blk>>>(x,  xh,  M_ * D_);
    f2h_kernel<<<D_ * D_ / 2048,   blk>>>(Wq, wqh, D_ * D_);
    f2h_kernel<<<KVD_ * D_ / 2048, blk>>>(Wk, wkh, KVD_ * D_);
    f2h_kernel<<<KVD_ * D_ / 2048, blk>>>(Wv, wvh, KVD_ * D_);
    f2h_kernel<<<D_ * D_ / 2048,   blk>>>(Wo, woh, D_ * D_);

    dim3 gq_grid(D_ / 128, M_ / 128);
    dim3 gkv_grid(KVD_ / 128, M_ / 128);

    gemm_nt_h_kernel<<<gq_grid,  blk, GEMM_SMEM_BYTES>>>(xh, wqh, gq, nullptr, M_, D_,   D_);
    gemm_nt_h_kernel<<<gkv_grid, blk, GEMM_SMEM_BYTES>>>(xh, wkh, gk, nullptr, M_, KVD_, D_);
    gemm_nt_h_kernel<<<gkv_grid, blk, GEMM_SMEM_BYTES>>>(xh, wvh, gv, nullptr, M_, KVD_, D_);

    rope_h_kernel<<<M_, blk>>>(gq, gk, cosT, sinT);

    dim3 ga(T_ / 128, H_, B_);
    attn_f16_kernel<<<ga, blk, ATTN_SMEM_BYTES>>>(gq, gk, gv, gattn);

    gemm_nt_h_kernel<<<gq_grid, blk, GEMM_SMEM_BYTES>>>(gattn, woh, nullptr, out, M_, D_, D_);
}

// round 14
// speedup vs baseline: 1.0209x; 1.0209x over previous
#include <cuda_runtime.h>
#include <cuda_fp16.h>
#include <math_constants.h>
#include <stdint.h>

// Problem constants
#define B_   2
#define T_   2048
#define D_   2048
#define H_   16
#define HKV_ 4
#define HD_  128
#define G_   (H_ / HKV_)      // 4
#define M_   (B_ * T_)        // 4096
#define KVD_ (HKV_ * HD_)     // 512
#define KVN_ (2 * KVD_)       // 1024 (combined K|V)

// ---------------------------------------------------------------------------
// Scratch (device globals; no allocation allowed) — all fp16
// ---------------------------------------------------------------------------
__device__ __half g_xh[(size_t)M_ * D_];      // 16 MB
__device__ __half g_wqh[(size_t)D_ * D_];     //  8 MB
__device__ __half g_wkvh[(size_t)KVN_ * D_];  //  4 MB (Wk rows 0-511, Wv rows 512-1023)
__device__ __half g_woh[(size_t)D_ * D_];     //  8 MB
__device__ __half g_q[(size_t)M_ * D_];       // 16 MB
__device__ __half g_kv[(size_t)M_ * KVN_];    //  8 MB (cols 0-511 K, 512-1023 V)
__device__ __half g_attn[(size_t)M_ * D_];    // 16 MB

// ---------------------------------------------------------------------------
// Helpers
// ---------------------------------------------------------------------------
__device__ __forceinline__ uint32_t pk_h2(float lo, float hi) {
    half2 h = __floats2half2_rn(lo, hi);
    return *(uint32_t*)&h;
}

__device__ __forceinline__ uint32_t smem_u32(const void* p) {
    uint32_t a;
    asm("{ .reg .u64 t; cvta.to.shared.u64 t, %1; cvt.u32.u64 %0, t; }"
        : "=r"(a) : "l"(p));
    return a;
}

#define MMA_F16(c, a, b)                                                      \
    asm volatile(                                                             \
        "mma.sync.aligned.m16n8k16.row.col.f32.f16.f16.f32 "                  \
        "{%0,%1,%2,%3},{%4,%5,%6,%7},{%8,%9},{%0,%1,%2,%3};"                  \
        : "+f"((c)[0]), "+f"((c)[1]), "+f"((c)[2]), "+f"((c)[3])              \
        : "r"((a)[0]), "r"((a)[1]), "r"((a)[2]), "r"((a)[3]),                 \
          "r"((b)[0]), "r"((b)[1]))

#define LDSM_X4(r0, r1, r2, r3, addr)                                         \
    asm volatile(                                                             \
        "ldmatrix.sync.aligned.m8n8.x4.shared.b16 {%0,%1,%2,%3}, [%4];"       \
        : "=r"(r0), "=r"(r1), "=r"(r2), "=r"(r3) : "r"(addr))

#define LDSM_X4_T(r0, r1, r2, r3, addr)                                       \
    asm volatile(                                                             \
        "ldmatrix.sync.aligned.m8n8.x4.trans.shared.b16 {%0,%1,%2,%3}, [%4];" \
        : "=r"(r0), "=r"(r1), "=r"(r2), "=r"(r3) : "r"(addr))

#define CP_ASYNC16(dst, src)                                                  \
    asm volatile("cp.async.cg.shared.global [%0], [%1], 16;"                  \
                 :: "r"(dst), "l"(src))
#define CP_COMMIT() asm volatile("cp.async.commit_group;" ::: "memory")
#define CP_WAIT0()  asm volatile("cp.async.wait_group 0;" ::: "memory")
#define CP_WAIT1()  asm volatile("cp.async.wait_group 1;" ::: "memory")

// ---------------------------------------------------------------------------
// Fused fp32->fp16 conversion: x | Wq | Wk | Wv | Wo in one launch.
// 2048 floats per block.
// ---------------------------------------------------------------------------
#define XB_   (M_ * D_ / 2048)        // 4096 blocks
#define WQB_  (D_ * D_ / 2048)        // 2048
#define WKB_  (KVD_ * D_ / 2048)      // 512
#define WVB_  (KVD_ * D_ / 2048)      // 512
#define WOB_  (D_ * D_ / 2048)        // 2048
#define F2H_BLOCKS (XB_ + WQB_ + WKB_ + WVB_ + WOB_)   // 9216

__global__ __launch_bounds__(256) void f2h_all_kernel(
    const float* __restrict__ x,  const float* __restrict__ Wq,
    const float* __restrict__ Wk, const float* __restrict__ Wv,
    const float* __restrict__ Wo,
    __half* __restrict__ xh, __half* __restrict__ wqh,
    __half* __restrict__ wkvh, __half* __restrict__ woh)
{
    int blk = blockIdx.x;
    const float* src;
    __half* dst;
    if (blk < XB_)                     { src = x;  dst = xh;   }
    else if ((blk -= XB_)  < WQB_)     { src = Wq; dst = wqh;  }
    else if ((blk -= WQB_) < WKB_)     { src = Wk; dst = wkvh; }
    else if ((blk -= WKB_) < WVB_)     { src = Wv; dst = wkvh + (size_t)KVD_ * D_; }
    else { blk -= WVB_;                  src = Wo; dst = woh;  }

    size_t i = ((size_t)blk * 256 + threadIdx.x) * 8;
    float4 a = *(const float4*)(src + i);
    float4 b = *(const float4*)(src + i + 4);
    uint4 o = { pk_h2(a.x, a.y), pk_h2(a.z, a.w),
                pk_h2(b.x, b.y), pk_h2(b.z, b.w) };
    *(uint4*)(dst + i) = o;
}

// ---------------------------------------------------------------------------
// fp16 tensor-core GEMM, 3-stage cp.async pipeline.
// ---------------------------------------------------------------------------
#define HSTRIDE 20
#define HROW_BYTES (HSTRIDE * 4)                 // 80
#define HTILE_WORDS (128 * HSTRIDE)              // 2560 u32 per tile
#define HTILE_BYTES (HTILE_WORDS * 4)            // 10240
#define GEMM_SMEM_BYTES (6 * HTILE_BYTES)        // 61440 B

__global__ __launch_bounds__(256) void gemm_nt_h_kernel(
    const __half* __restrict__ A, const __half* __restrict__ Bm,
    __half* __restrict__ Ch, float* __restrict__ Cf, int M, int N, int K)
{
    extern __shared__ uint32_t smw[];
    const uint32_t smBase = smem_u32(smw);

    const int tid  = threadIdx.x;
    const int lane = tid & 31;
    const int warp = tid >> 5;
    const int row0 = blockIdx.y * 128;
    const int col0 = blockIdx.x * 128;
    const int wm   = (warp >> 2) * 64;
    const int wn   = (warp & 3) * 32;
    const int lk   = lane & 3;
    const int lr   = lane >> 2;

    const uint32_t aoff = (uint32_t)(lane & 15) * HROW_BYTES + (uint32_t)(lane >> 4) * 16;
    const uint32_t boff = ((uint32_t)((lane >> 4) * 8 + (lane & 7))) * HROW_BYTES
                        + (uint32_t)((lane >> 3) & 1) * 16;

    int mL[2], hcL[2];
    uint32_t stA[2], stB[2];
#pragma unroll
    for (int t = 0; t < 2; t++) {
        int idx = tid + 256 * t;
        mL[t]  = idx >> 2;
        hcL[t] = (idx & 3) << 3;
        uint32_t wb = (uint32_t)(mL[t] * HSTRIDE + ((idx & 3) << 2)) * 4;
        stA[t] = smBase + wb;
        stB[t] = smBase + 3 * HTILE_BYTES + wb;
    }

    float c[4][4][4];
#pragma unroll
    for (int mi = 0; mi < 4; mi++)
#pragma unroll
        for (int ni = 0; ni < 4; ni++)
#pragma unroll
            for (int r = 0; r < 4; r++) c[mi][ni][r] = 0.f;

    const int niter = K >> 5;

#pragma unroll
    for (int st = 0; st < 2; st++) {
        const int k0 = st << 5;
        const uint32_t bo = (uint32_t)st * HTILE_BYTES;
#pragma unroll
        for (int t = 0; t < 2; t++) {
            CP_ASYNC16(stA[t] + bo, &A [(size_t)(row0 + mL[t]) * K + k0 + hcL[t]]);
            CP_ASYNC16(stB[t] + bo, &Bm[(size_t)(col0 + mL[t]) * K + k0 + hcL[t]]);
        }
        CP_COMMIT();
    }

    int buf = 0;
    for (int it = 0; it < niter; ++it) {
        CP_WAIT1();
        __syncthreads();

        if (it + 2 < niter) {
            int nb = buf + 2; if (nb >= 3) nb -= 3;
            const int k0 = (it + 2) << 5;
            const uint32_t bo = (uint32_t)nb * HTILE_BYTES;
#pragma unroll
            for (int t = 0; t < 2; t++) {
                CP_ASYNC16(stA[t] + bo, &A [(size_t)(row0 + mL[t]) * K + k0 + hcL[t]]);
                CP_ASYNC16(stB[t] + bo, &Bm[(size_t)(col0 + mL[t]) * K + k0 + hcL[t]]);
            }
            CP_COMMIT();
        }

        const uint32_t aB = smBase + (uint32_t)buf * HTILE_BYTES + aoff;
        const uint32_t bB = smBase + (uint32_t)(3 + buf) * HTILE_BYTES + boff;
#pragma unroll
        for (int s = 0; s < 2; s++) {
            const uint32_t so = (uint32_t)s * 32;
            uint32_t af[4][4], bf[4][2];
#pragma unroll
            for (int mi = 0; mi < 4; mi++)
                LDSM_X4(af[mi][0], af[mi][1], af[mi][2], af[mi][3],
                        aB + (uint32_t)(wm + 16 * mi) * HROW_BYTES + so);
#pragma unroll
            for (int p = 0; p < 2; p++)
                LDSM_X4(bf[2 * p][0], bf[2 * p][1], bf[2 * p + 1][0], bf[2 * p + 1][1],
                        bB + (uint32_t)(wn + 16 * p) * HROW_BYTES + so);
#pragma unroll
            for (int mi = 0; mi < 4; mi++)
#pragma unroll
                for (int ni = 0; ni < 4; ni++)
                    MMA_F16(c[mi][ni], af[mi], bf[ni]);
        }
        __syncthreads();
        if (++buf == 3) buf = 0;
    }

#pragma unroll
    for (int mi = 0; mi < 4; mi++) {
#pragma unroll
        for (int ni = 0; ni < 4; ni++) {
            int r  = row0 + wm + 16 * mi + lr;
            int cc = col0 + wn + 8 * ni + 2 * lk;
            if (Ch) {
                *(uint32_t*)&Ch[(size_t)r * N + cc]       = pk_h2(c[mi][ni][0], c[mi][ni][1]);
                *(uint32_t*)&Ch[(size_t)(r + 8) * N + cc] = pk_h2(c[mi][ni][2], c[mi][ni][3]);
            } else {
                Cf[(size_t)r * N + cc]           = c[mi][ni][0];
                Cf[(size_t)r * N + cc + 1]       = c[mi][ni][1];
                Cf[(size_t)(r + 8) * N + cc]     = c[mi][ni][2];
                Cf[(size_t)(r + 8) * N + cc + 1] = c[mi][ni][3];
            }
        }
    }
}

// ---------------------------------------------------------------------------
// RoPE on half buffers; K lives in combined KV buffer (stride KVN_, cols 0-511).
// Folds 1/sqrt(HD) scale into Q.
// ---------------------------------------------------------------------------
__global__ __launch_bounds__(256) void rope_h_kernel(
    __half* __restrict__ q, __half* __restrict__ kv,
    const float* __restrict__ cosT, const float* __restrict__ sinT)
{
    const int bt  = blockIdx.x;
    const int t   = bt & (T_ - 1);
    const int tid = threadIdx.x;
    const float scale = 0.08838834764831845f;
    const float* cr = cosT + (size_t)t * HD_;
    const float* sr = sinT + (size_t)t * HD_;

    __half* qrow = q + (size_t)bt * D_;
    for (int p = tid; p < H_ * 64; p += 256) {
        int h = p >> 6, i = p & 63;
        __half* base = qrow + h * HD_;
        float q1 = __half2float(base[i]), q2 = __half2float(base[i + 64]);
        base[i]      = __float2half_rn((q1 * cr[i]      - q2 * sr[i]) * scale);
        base[i + 64] = __float2half_rn((q2 * cr[i + 64] + q1 * sr[i + 64]) * scale);
    }
    __half* krow = kv + (size_t)bt * KVN_;
    for (int p = tid; p < HKV_ * 64; p += 256) {
        int h = p >> 6, i = p & 63;
        __half* base = krow + h * HD_;
        float k1 = __half2float(base[i]), k2 = __half2float(base[i + 64]);
        base[i]      = __float2half_rn(k1 * cr[i]      - k2 * sr[i]);
        base[i + 64] = __float2half_rn(k2 * cr[i + 64] + k1 * sr[i + 64]);
    }
}

// ---------------------------------------------------------------------------
// fp16 flash attention, BK=128, cp.async double-buffered K/V.
// Grid: (T/128, H, B). Block: 256 = 8 warps; warp w owns q-rows [w*16,w*16+16).
// Smem: two buffers of { Ks[128][68], Vs[128][68] } u32 words (69632 B each).
// K/V loader: 2 threads per key row, 8 x 16B cp.async each = full 256 B row.
// ---------------------------------------------------------------------------
#define AT_TILE_WORDS 8704                    // 128 rows x 68 words
#define AT_BUF_WORDS (2 * AT_TILE_WORDS)      // Ks + Vs
#define AT_BUF_BYTES (AT_BUF_WORDS * 4)       // 69632
#define AT_VS_BOFF   (AT_TILE_WORDS * 4)      // 34816
#define ATTN_SMEM_BYTES (2 * AT_BUF_BYTES)    // 139264
#define KS_ROW_BYTES 272                      // 68 words

__global__ __launch_bounds__(256, 1) void attn_f16_kernel(
    const __half* __restrict__ q, const __half* __restrict__ kv,
    __half* __restrict__ o)
{
    extern __shared__ uint32_t sw[];
    uint32_t* Qs = sw;                 // staging [128][68], aliases buffer 0

    const int qt  = (int)(gridDim.x - 1 - blockIdx.x);   // heavy tiles first
    const int h   = blockIdx.y;
    const int b   = blockIdx.z;
    const int kvh = h >> 2;
    const int q0  = qt * 128;
    const int tid  = threadIdx.x;
    const int lane = tid & 31;
    const int w    = tid >> 5;
    const int lr   = lane >> 2;
    const int lk   = lane & 3;

    const uint32_t smB = smem_u32(sw);
    const uint32_t brow   = (uint32_t)((lane >> 4) * 8 + (lane & 7));
    const uint32_t bcol16 = (uint32_t)((lane >> 3) & 1) * 16;
    const uint32_t arow   = (uint32_t)(lane & 15);
    const uint32_t asel16 = (uint32_t)(lane >> 4) * 16;

    // per-thread K/V load coords: 2 threads per key row, 64 halves (128 B) each
    const int krow = tid >> 1;                  // key 0..127
    const int kd0  = (tid & 1) * 64;            // halves
    const uint32_t kvw = (uint32_t)(krow * 68 + (kd0 >> 1)) * 4;

    // ---- stage Q (half, scale pre-folded) and pull A-fragments ----
    {
        int row = tid >> 1;
        int d0  = (tid & 1) * 64;
        const __half* src = q + (size_t)(b * T_ + q0 + row) * D_ + h * HD_ + d0;
#pragma unroll
        for (int j = 0; j < 64; j += 8)
            *(uint4*)&Qs[row * 68 + ((d0 + j) >> 1)] = *(const uint4*)(src + j);
    }
    __syncthreads();

    uint32_t aQ[8][4];
#pragma unroll
    for (int c = 0; c < 8; c++)
        LDSM_X4(aQ[c][0], aQ[c][1], aQ[c][2], aQ[c][3],
                smB + (uint32_t)(w * 16 + arow) * KS_ROW_BYTES
                    + (uint32_t)c * 32 + asel16);
    __syncthreads();

    float O[16][4];
#pragma unroll
    for (int nt = 0; nt < 16; nt++)
#pragma unroll
        for (int r = 0; r < 4; r++) O[nt][r] = 0.f;
    float m0 = -CUDART_INF_F, m1 = -CUDART_INF_F, l0 = 0.f, l1 = 0.f;

    const int row0g = q0 + w * 16 + lr;
    const int nkt = qt + 1;          // BK=128 tiles

    const __half* kbase = kv + (size_t)(b * T_ + krow) * KVN_ + kvh * HD_ + kd0;
    const __half* vbase = kbase + KVD_;

    // prologue: async-load tile 0 into buffer 0 (8 x 16B per thread per tensor)
#pragma unroll
    for (int j = 0; j < 8; j++) {
        CP_ASYNC16(smB + kvw + 16u * j,               kbase + 8 * j);
        CP_ASYNC16(smB + AT_VS_BOFF + kvw + 16u * j,  vbase + 8 * j);
    }
    CP_COMMIT();
    CP_WAIT0();
    __syncthreads();

    for (int kt = 0; kt < nkt; kt++) {
        const uint32_t bufB = smB + (uint32_t)(kt & 1) * AT_BUF_BYTES;

        if (kt + 1 < nkt) {
            const uint32_t nb = smB + (uint32_t)((kt + 1) & 1) * AT_BUF_BYTES;
            const size_t goff = (size_t)(kt + 1) * 128 * KVN_;
#pragma unroll
            for (int j = 0; j < 8; j++) {
                CP_ASYNC16(nb + kvw + 16u * j,              kbase + goff + 8 * j);
                CP_ASYNC16(nb + AT_VS_BOFF + kvw + 16u * j, vbase + goff + 8 * j);
            }
            CP_COMMIT();
        }

        const int k0 = kt * 128;
        const bool active = (k0 <= q0 + w * 16 + 15);   // warp-uniform
        if (active) {
            const uint32_t KsB = bufB;
            const uint32_t VsB = bufB + AT_VS_BOFF;

            // ---- S = Q K^T  (16 q-rows x 128 keys) ----
            float s[16][4];
#pragma unroll
            for (int nt = 0; nt < 16; nt++)
#pragma unroll
                for (int r = 0; r < 4; r++) s[nt][r] = 0.f;

#pragma unroll
            for (int c = 0; c < 8; c++) {
                uint32_t bf[16][2];
#pragma unroll
                for (int p = 0; p < 8; p++)
                    LDSM_X4(bf[2 * p][0], bf[2 * p][1], bf[2 * p + 1][0], bf[2 * p + 1][1],
                            KsB + (uint32_t)(p * 16 + brow) * KS_ROW_BYTES
                                + (uint32_t)c * 32 + bcol16);
#pragma unroll
                for (int nt = 0; nt < 16; nt++)
                    MMA_F16(s[nt], aQ[c], bf[nt]);
            }

            // ---- causal mask ----
            if (k0 + 127 > q0 + w * 16) {
#pragma unroll
                for (int nt = 0; nt < 16; nt++) {
                    int c0 = k0 + nt * 8 + 2 * lk;
                    if (c0     > row0g)     s[nt][0] = -CUDART_INF_F;
                    if (c0 + 1 > row0g)     s[nt][1] = -CUDART_INF_F;
                    if (c0     > row0g + 8) s[nt][2] = -CUDART_INF_F;
                    if (c0 + 1 > row0g + 8) s[nt][3] = -CUDART_INF_F;
                }
            }

            // ---- online softmax ----
            float mt0 = -CUDART_INF_F, mt1 = -CUDART_INF_F;
#pragma unroll
            for (int nt = 0; nt < 16; nt++) {
                mt0 = fmaxf(mt0, fmaxf(s[nt][0], s[nt][1]));
                mt1 = fmaxf(mt1, fmaxf(s[nt][2], s[nt][3]));
            }
#pragma unroll
            for (int off = 1; off <= 2; off <<= 1) {
                mt0 = fmaxf(mt0, __shfl_xor_sync(0xffffffffu, mt0, off));
                mt1 = fmaxf(mt1, __shfl_xor_sync(0xffffffffu, mt1, off));
            }
            float mn0 = fmaxf(m0, mt0), mn1 = fmaxf(m1, mt1);
            float al0 = __expf(m0 - mn0), al1 = __expf(m1 - mn1);
            m0 = mn0; m1 = mn1;

            float sum0 = 0.f, sum1 = 0.f;
#pragma unroll
            for (int nt = 0; nt < 16; nt++) {
                s[nt][0] = __expf(s[nt][0] - mn0); sum0 += s[nt][0];
                s[nt][1] = __expf(s[nt][1] - mn0); sum0 += s[nt][1];
                s[nt][2] = __expf(s[nt][2] - mn1); sum1 += s[nt][2];
                s[nt][3] = __expf(s[nt][3] - mn1); sum1 += s[nt][3];
            }
#pragma unroll
            for (int off = 1; off <= 2; off <<= 1) {
                sum0 += __shfl_xor_sync(0xffffffffu, sum0, off);
                sum1 += __shfl_xor_sync(0xffffffffu, sum1, off);
            }
            l0 = l0 * al0 + sum0;
            l1 = l1 * al1 + sum1;
#pragma unroll
            for (int nt = 0; nt < 16; nt++) {
                O[nt][0] *= al0; O[nt][1] *= al0;
                O[nt][2] *= al1; O[nt][3] *= al1;
            }

            // ---- O += P V  (P in registers; V frags via ldmatrix.trans) ----
#pragma unroll
            for (int c = 0; c < 8; c++) {
                uint32_t pa[4];
                pa[0] = pk_h2(s[2 * c][0],     s[2 * c][1]);
                pa[1] = pk_h2(s[2 * c][2],     s[2 * c][3]);
                pa[2] = pk_h2(s[2 * c + 1][0], s[2 * c + 1][1]);
                pa[3] = pk_h2(s[2 * c + 1][2], s[2 * c + 1][3]);
#pragma unroll
                for (int p = 0; p < 8; p++) {
                    uint32_t vb[2][2];
                    LDSM_X4_T(vb[0][0], vb[0][1], vb[1][0], vb[1][1],
                              VsB + (uint32_t)(c * 16 + arow) * KS_ROW_BYTES
                                  + (uint32_t)p * 32 + asel16);
                    MMA_F16(O[2 * p],     pa, vb[0]);
                    MMA_F16(O[2 * p + 1], pa, vb[1]);
                }
            }
        }

        if (kt + 1 < nkt) CP_WAIT0();
        __syncthreads();
    }

    // ---- epilogue (half out) ----
    float inv0 = 1.0f / l0, inv1 = 1.0f / l1;
    size_t r0base = (size_t)(b * T_ + q0 + w * 16 + lr) * D_ + h * HD_;
    size_t r1base = (size_t)(b * T_ + q0 + w * 16 + lr + 8) * D_ + h * HD_;
#pragma unroll
    for (int nt = 0; nt < 16; nt++) {
        *(uint32_t*)&o[r0base + nt * 8 + 2 * lk] = pk_h2(O[nt][0] * inv0, O[nt][1] * inv0);
        *(uint32_t*)&o[r1base + nt * 8 + 2 * lk] = pk_h2(O[nt][2] * inv1, O[nt][3] * inv1);
    }
}

// ---------------------------------------------------------------------------
// Launcher
// ---------------------------------------------------------------------------
extern "C" void kernel_launch(void* const* d_in, const int* in_sizes, int n_in,
                              void* d_out, int out_size)
{
    const float* x    = (const float*)d_in[0];
    const float* cosT = (const float*)d_in[1];
    const float* sinT = (const float*)d_in[2];
    const float* Wq   = (const float*)d_in[3];
    const float* Wk   = (const float*)d_in[4];
    const float* Wv   = (const float*)d_in[5];
    const float* Wo   = (const float*)d_in[6];
    float* out = (float*)d_out;

    __half *xh, *wqh, *wkvh, *woh, *gq, *gkv, *gattn;
    cudaGetSymbolAddress((void**)&xh,    g_xh);
    cudaGetSymbolAddress((void**)&wqh,   g_wqh);
    cudaGetSymbolAddress((void**)&wkvh,  g_wkvh);
    cudaGetSymbolAddress((void**)&woh,   g_woh);
    cudaGetSymbolAddress((void**)&gq,    g_q);
    cudaGetSymbolAddress((void**)&gkv,   g_kv);
    cudaGetSymbolAddress((void**)&gattn, g_attn);

    cudaFuncSetAttribute(attn_f16_kernel, cudaFuncAttributeMaxDynamicSharedMemorySize,
                         ATTN_SMEM_BYTES);
    cudaFuncSetAttribute(gemm_nt_h_kernel,
                         cudaFuncAttributeMaxDynamicSharedMemorySize,
                         GEMM_SMEM_BYTES);

    dim3 blk(256);
    f2h_all_kernel<<<F2H_BLOCKS, blk>>>(x, Wq, Wk, Wv, Wo, xh, wqh, wkvh, woh);

    dim3 gq_grid(D_ / 128, M_ / 128);
    dim3 gkv_grid(KVN_ / 128, M_ / 128);

    gemm_nt_h_kernel<<<gq_grid,  blk, GEMM_SMEM_BYTES>>>(xh, wqh,  gq,  nullptr, M_, D_,   D_);
    gemm_nt_h_kernel<<<gkv_grid, blk, GEMM_SMEM_BYTES>>>(xh, wkvh, gkv, nullptr, M_, KVN_, D_);

    rope_h_kernel<<<M_, blk>>>(gq, gkv, cosT, sinT);

    dim3 ga(T_ / 128, H_, B_);
    attn_f16_kernel<<<ga, blk, ATTN_SMEM_BYTES>>>(gq, gkv, gattn);

    gemm_nt_h_kernel<<<gq_grid, blk, GEMM_SMEM_BYTES>>>(gattn, woh, nullptr, out, M_, D_, D_);
}

// round 15
// speedup vs baseline: 1.0244x; 1.0035x over previous
#include <cuda_runtime.h>
#include <cuda_fp16.h>
#include <math_constants.h>
#include <stdint.h>

// Problem constants
#define B_   2
#define T_   2048
#define D_   2048
#define H_   16
#define HKV_ 4
#define HD_  128
#define G_   (H_ / HKV_)      // 4
#define M_   (B_ * T_)        // 4096
#define KVD_ (HKV_ * HD_)     // 512
#define QKVN_ (D_ + 2 * KVD_) // 3072 (combined Q|K|V output width)

// ---------------------------------------------------------------------------
// Scratch (device globals; no allocation allowed) — all fp16
// ---------------------------------------------------------------------------
__device__ __half g_xh[(size_t)M_ * D_];        // 16 MB
__device__ __half g_wqkvh[(size_t)QKVN_ * D_];  // 12 MB (Wq 0-2047 | Wk 2048-2559 | Wv 2560-3071)
__device__ __half g_woh[(size_t)D_ * D_];       //  8 MB
__device__ __half g_qkv[(size_t)M_ * QKVN_];    // 24 MB (Q 0-2047 | K 2048-2559 | V 2560-3071)
__device__ __half g_attn[(size_t)M_ * D_];      // 16 MB

// ---------------------------------------------------------------------------
// Helpers
// ---------------------------------------------------------------------------
__device__ __forceinline__ uint32_t pk_h2(float lo, float hi) {
    half2 h = __floats2half2_rn(lo, hi);
    return *(uint32_t*)&h;
}

__device__ __forceinline__ uint32_t smem_u32(const void* p) {
    uint32_t a;
    asm("{ .reg .u64 t; cvta.to.shared.u64 t, %1; cvt.u32.u64 %0, t; }"
        : "=r"(a) : "l"(p));
    return a;
}

// exp2 of packed (lo,hi) minus mh, in f16x2; returns A-frag-ready word
__device__ __forceinline__ uint32_t exp2_pair(float lo, float hi, half2 mh) {
    half2 v = h2exp2(__hsub2(__floats2half2_rn(lo, hi), mh));
    return *(uint32_t*)&v;
}

#define MMA_F16(c, a, b)                                                      \
    asm volatile(                                                             \
        "mma.sync.aligned.m16n8k16.row.col.f32.f16.f16.f32 "                  \
        "{%0,%1,%2,%3},{%4,%5,%6,%7},{%8,%9},{%0,%1,%2,%3};"                  \
        : "+f"((c)[0]), "+f"((c)[1]), "+f"((c)[2]), "+f"((c)[3])              \
        : "r"((a)[0]), "r"((a)[1]), "r"((a)[2]), "r"((a)[3]),                 \
          "r"((b)[0]), "r"((b)[1]))

#define LDSM_X4(r0, r1, r2, r3, addr)                                         \
    asm volatile(                                                             \
        "ldmatrix.sync.aligned.m8n8.x4.shared.b16 {%0,%1,%2,%3}, [%4];"       \
        : "=r"(r0), "=r"(r1), "=r"(r2), "=r"(r3) : "r"(addr))

#define LDSM_X4_T(r0, r1, r2, r3, addr)                                       \
    asm volatile(                                                             \
        "ldmatrix.sync.aligned.m8n8.x4.trans.shared.b16 {%0,%1,%2,%3}, [%4];" \
        : "=r"(r0), "=r"(r1), "=r"(r2), "=r"(r3) : "r"(addr))

#define CP_ASYNC16(dst, src)                                                  \
    asm volatile("cp.async.cg.shared.global [%0], [%1], 16;"                  \
                 :: "r"(dst), "l"(src))
#define CP_COMMIT() asm volatile("cp.async.commit_group;" ::: "memory")
#define CP_WAIT0()  asm volatile("cp.async.wait_group 0;" ::: "memory")
#define CP_WAIT1()  asm volatile("cp.async.wait_group 1;" ::: "memory")

// ---------------------------------------------------------------------------
// Fused fp32->fp16 conversion: x | Wq | Wk | Wv | Wo in one launch.
// ---------------------------------------------------------------------------
#define XB_   (M_ * D_ / 2048)        // 4096 blocks
#define WQB_  (D_ * D_ / 2048)        // 2048
#define WKB_  (KVD_ * D_ / 2048)      // 512
#define WVB_  (KVD_ * D_ / 2048)      // 512
#define WOB_  (D_ * D_ / 2048)        // 2048
#define F2H_BLOCKS (XB_ + WQB_ + WKB_ + WVB_ + WOB_)   // 9216

__global__ __launch_bounds__(256) void f2h_all_kernel(
    const float* __restrict__ x,  const float* __restrict__ Wq,
    const float* __restrict__ Wk, const float* __restrict__ Wv,
    const float* __restrict__ Wo,
    __half* __restrict__ xh, __half* __restrict__ wqkvh,
    __half* __restrict__ woh)
{
    int blk = blockIdx.x;
    const float* src;
    __half* dst;
    if (blk < XB_)                     { src = x;  dst = xh;    }
    else if ((blk -= XB_)  < WQB_)     { src = Wq; dst = wqkvh; }
    else if ((blk -= WQB_) < WKB_)     { src = Wk; dst = wqkvh + (size_t)D_ * D_; }
    else if ((blk -= WKB_) < WVB_)     { src = Wv; dst = wqkvh + (size_t)(D_ + KVD_) * D_; }
    else { blk -= WVB_;                  src = Wo; dst = woh;   }

    size_t i = ((size_t)blk * 256 + threadIdx.x) * 8;
    float4 a = *(const float4*)(src + i);
    float4 b = *(const float4*)(src + i + 4);
    uint4 o = { pk_h2(a.x, a.y), pk_h2(a.z, a.w),
                pk_h2(b.x, b.y), pk_h2(b.z, b.w) };
    *(uint4*)(dst + i) = o;
}

// ---------------------------------------------------------------------------
// fp16 tensor-core GEMM, 3-stage cp.async pipeline (unchanged).
// ---------------------------------------------------------------------------
#define HSTRIDE 20
#define HROW_BYTES (HSTRIDE * 4)                 // 80
#define HTILE_WORDS (128 * HSTRIDE)              // 2560 u32 per tile
#define HTILE_BYTES (HTILE_WORDS * 4)            // 10240
#define GEMM_SMEM_BYTES (6 * HTILE_BYTES)        // 61440 B

__global__ __launch_bounds__(256) void gemm_nt_h_kernel(
    const __half* __restrict__ A, const __half* __restrict__ Bm,
    __half* __restrict__ Ch, float* __restrict__ Cf, int M, int N, int K)
{
    extern __shared__ uint32_t smw[];
    const uint32_t smBase = smem_u32(smw);

    const int tid  = threadIdx.x;
    const int lane = tid & 31;
    const int warp = tid >> 5;
    const int row0 = blockIdx.y * 128;
    const int col0 = blockIdx.x * 128;
    const int wm   = (warp >> 2) * 64;
    const int wn   = (warp & 3) * 32;
    const int lk   = lane & 3;
    const int lr   = lane >> 2;

    const uint32_t aoff = (uint32_t)(lane & 15) * HROW_BYTES + (uint32_t)(lane >> 4) * 16;
    const uint32_t boff = ((uint32_t)((lane >> 4) * 8 + (lane & 7))) * HROW_BYTES
                        + (uint32_t)((lane >> 3) & 1) * 16;

    int mL[2], hcL[2];
    uint32_t stA[2], stB[2];
#pragma unroll
    for (int t = 0; t < 2; t++) {
        int idx = tid + 256 * t;
        mL[t]  = idx >> 2;
        hcL[t] = (idx & 3) << 3;
        uint32_t wb = (uint32_t)(mL[t] * HSTRIDE + ((idx & 3) << 2)) * 4;
        stA[t] = smBase + wb;
        stB[t] = smBase + 3 * HTILE_BYTES + wb;
    }

    float c[4][4][4];
#pragma unroll
    for (int mi = 0; mi < 4; mi++)
#pragma unroll
        for (int ni = 0; ni < 4; ni++)
#pragma unroll
            for (int r = 0; r < 4; r++) c[mi][ni][r] = 0.f;

    const int niter = K >> 5;

#pragma unroll
    for (int st = 0; st < 2; st++) {
        const int k0 = st << 5;
        const uint32_t bo = (uint32_t)st * HTILE_BYTES;
#pragma unroll
        for (int t = 0; t < 2; t++) {
            CP_ASYNC16(stA[t] + bo, &A [(size_t)(row0 + mL[t]) * K + k0 + hcL[t]]);
            CP_ASYNC16(stB[t] + bo, &Bm[(size_t)(col0 + mL[t]) * K + k0 + hcL[t]]);
        }
        CP_COMMIT();
    }

    int buf = 0;
    for (int it = 0; it < niter; ++it) {
        CP_WAIT1();
        __syncthreads();

        if (it + 2 < niter) {
            int nb = buf + 2; if (nb >= 3) nb -= 3;
            const int k0 = (it + 2) << 5;
            const uint32_t bo = (uint32_t)nb * HTILE_BYTES;
#pragma unroll
            for (int t = 0; t < 2; t++) {
                CP_ASYNC16(stA[t] + bo, &A [(size_t)(row0 + mL[t]) * K + k0 + hcL[t]]);
                CP_ASYNC16(stB[t] + bo, &Bm[(size_t)(col0 + mL[t]) * K + k0 + hcL[t]]);
            }
            CP_COMMIT();
        }

        const uint32_t aB = smBase + (uint32_t)buf * HTILE_BYTES + aoff;
        const uint32_t bB = smBase + (uint32_t)(3 + buf) * HTILE_BYTES + boff;
#pragma unroll
        for (int s = 0; s < 2; s++) {
            const uint32_t so = (uint32_t)s * 32;
            uint32_t af[4][4], bf[4][2];
#pragma unroll
            for (int mi = 0; mi < 4; mi++)
                LDSM_X4(af[mi][0], af[mi][1], af[mi][2], af[mi][3],
                        aB + (uint32_t)(wm + 16 * mi) * HROW_BYTES + so);
#pragma unroll
            for (int p = 0; p < 2; p++)
                LDSM_X4(bf[2 * p][0], bf[2 * p][1], bf[2 * p + 1][0], bf[2 * p + 1][1],
                        bB + (uint32_t)(wn + 16 * p) * HROW_BYTES + so);
#pragma unroll
            for (int mi = 0; mi < 4; mi++)
#pragma unroll
                for (int ni = 0; ni < 4; ni++)
                    MMA_F16(c[mi][ni], af[mi], bf[ni]);
        }
        __syncthreads();
        if (++buf == 3) buf = 0;
    }

#pragma unroll
    for (int mi = 0; mi < 4; mi++) {
#pragma unroll
        for (int ni = 0; ni < 4; ni++) {
            int r  = row0 + wm + 16 * mi + lr;
            int cc = col0 + wn + 8 * ni + 2 * lk;
            if (Ch) {
                *(uint32_t*)&Ch[(size_t)r * N + cc]       = pk_h2(c[mi][ni][0], c[mi][ni][1]);
                *(uint32_t*)&Ch[(size_t)(r + 8) * N + cc] = pk_h2(c[mi][ni][2], c[mi][ni][3]);
            } else {
                Cf[(size_t)r * N + cc]           = c[mi][ni][0];
                Cf[(size_t)r * N + cc + 1]       = c[mi][ni][1];
                Cf[(size_t)(r + 8) * N + cc]     = c[mi][ni][2];
                Cf[(size_t)(r + 8) * N + cc + 1] = c[mi][ni][3];
            }
        }
    }
}

// ---------------------------------------------------------------------------
// RoPE on combined QKV buffer (row stride QKVN_). Q cols 0-2047, K 2048-2559.
// Folds (1/sqrt(HD)) * log2(e) into Q (scores in log2 domain downstream).
// ---------------------------------------------------------------------------
__global__ __launch_bounds__(256) void rope_h_kernel(
    __half* __restrict__ qkv,
    const float* __restrict__ cosT, const float* __restrict__ sinT)
{
    const int bt  = blockIdx.x;
    const int t   = bt & (T_ - 1);
    const int tid = threadIdx.x;
    const float scale = 0.08838834764831845f * 1.4426950408889634f;  // /sqrt(128) * log2e
    const float* cr = cosT + (size_t)t * HD_;
    const float* sr = sinT + (size_t)t * HD_;

    __half* qrow = qkv + (size_t)bt * QKVN_;
    for (int p = tid; p < H_ * 64; p += 256) {
        int h = p >> 6, i = p & 63;
        __half* base = qrow + h * HD_;
        float q1 = __half2float(base[i]), q2 = __half2float(base[i + 64]);
        base[i]      = __float2half_rn((q1 * cr[i]      - q2 * sr[i]) * scale);
        base[i + 64] = __float2half_rn((q2 * cr[i + 64] + q1 * sr[i + 64]) * scale);
    }
    __half* krow = qrow + D_;
    for (int p = tid; p < HKV_ * 64; p += 256) {
        int h = p >> 6, i = p & 63;
        __half* base = krow + h * HD_;
        float k1 = __half2float(base[i]), k2 = __half2float(base[i + 64]);
        base[i]      = __float2half_rn(k1 * cr[i]      - k2 * sr[i]);
        base[i + 64] = __float2half_rn(k2 * cr[i + 64] + k1 * sr[i + 64]);
    }
}

// ---------------------------------------------------------------------------
// fp16 flash attention, BK=128, log2-domain softmax with f16x2 exp2 and
// ones-MMA row sums. K/V from combined QKV buffer (row stride QKVN_).
// ---------------------------------------------------------------------------
#define AT_TILE_WORDS 8704                    // 128 rows x 68 words
#define AT_BUF_WORDS (2 * AT_TILE_WORDS)      // Ks + Vs
#define AT_BUF_BYTES (AT_BUF_WORDS * 4)       // 69632
#define AT_VS_BOFF   (AT_TILE_WORDS * 4)      // 34816
#define ATTN_SMEM_BYTES (2 * AT_BUF_BYTES)    // 139264
#define KS_ROW_BYTES 272                      // 68 words

__global__ __launch_bounds__(256, 1) void attn_f16_kernel(
    const __half* __restrict__ qkv, __half* __restrict__ o)
{
    extern __shared__ uint32_t sw[];
    uint32_t* Qs = sw;                 // staging [128][68], aliases buffer 0

    const int qt  = (int)(gridDim.x - 1 - blockIdx.x);
    const int h   = blockIdx.y;
    const int b   = blockIdx.z;
    const int kvh = h >> 2;
    const int q0  = qt * 128;
    const int tid  = threadIdx.x;
    const int lane = tid & 31;
    const int w    = tid >> 5;
    const int lr   = lane >> 2;
    const int lk   = lane & 3;

    const uint32_t smB = smem_u32(sw);
    const uint32_t brow   = (uint32_t)((lane >> 4) * 8 + (lane & 7));
    const uint32_t bcol16 = (uint32_t)((lane >> 3) & 1) * 16;
    const uint32_t arow   = (uint32_t)(lane & 15);
    const uint32_t asel16 = (uint32_t)(lane >> 4) * 16;

    // per-thread K/V load coords: 2 threads per key row, 64 halves (128 B) each
    const int krow = tid >> 1;
    const int kd0  = (tid & 1) * 64;
    const uint32_t kvw = (uint32_t)(krow * 68 + (kd0 >> 1)) * 4;

    // ---- stage Q (log2e*scale pre-folded) and pull A-fragments ----
    {
        int row = tid >> 1;
        int d0  = (tid & 1) * 64;
        const __half* src = qkv + (size_t)(b * T_ + q0 + row) * QKVN_ + h * HD_ + d0;
#pragma unroll
        for (int j = 0; j < 64; j += 8)
            *(uint4*)&Qs[row * 68 + ((d0 + j) >> 1)] = *(const uint4*)(src + j);
    }
    __syncthreads();

    uint32_t aQ[8][4];
#pragma unroll
    for (int c = 0; c < 8; c++)
        LDSM_X4(aQ[c][0], aQ[c][1], aQ[c][2], aQ[c][3],
                smB + (uint32_t)(w * 16 + arow) * KS_ROW_BYTES
                    + (uint32_t)c * 32 + asel16);
    __syncthreads();

    float O[16][4];
#pragma unroll
    for (int nt = 0; nt < 16; nt++)
#pragma unroll
        for (int r = 0; r < 4; r++) O[nt][r] = 0.f;
    float m0 = -CUDART_INF_F, m1 = -CUDART_INF_F, l0 = 0.f, l1 = 0.f;

    const int row0g = q0 + w * 16 + lr;
    const int nkt = qt + 1;

    const __half* kbase = qkv + (size_t)(b * T_ + krow) * QKVN_ + D_ + kvh * HD_ + kd0;
    const __half* vbase = kbase + KVD_;

    // prologue: async-load tile 0 (8 x 16B per thread per tensor)
#pragma unroll
    for (int j = 0; j < 8; j++) {
        CP_ASYNC16(smB + kvw + 16u * j,               kbase + 8 * j);
        CP_ASYNC16(smB + AT_VS_BOFF + kvw + 16u * j,  vbase + 8 * j);
    }
    CP_COMMIT();
    CP_WAIT0();
    __syncthreads();

    const uint32_t oneh2 = 0x3C003C00u;      // half2(1,1)

    for (int kt = 0; kt < nkt; kt++) {
        const uint32_t bufB = smB + (uint32_t)(kt & 1) * AT_BUF_BYTES;

        if (kt + 1 < nkt) {
            const uint32_t nb = smB + (uint32_t)((kt + 1) & 1) * AT_BUF_BYTES;
            const size_t goff = (size_t)(kt + 1) * 128 * QKVN_;
#pragma unroll
            for (int j = 0; j < 8; j++) {
                CP_ASYNC16(nb + kvw + 16u * j,              kbase + goff + 8 * j);
                CP_ASYNC16(nb + AT_VS_BOFF + kvw + 16u * j, vbase + goff + 8 * j);
            }
            CP_COMMIT();
        }

        const int k0 = kt * 128;
        const bool active = (k0 <= q0 + w * 16 + 15);
        if (active) {
            const uint32_t KsB = bufB;
            const uint32_t VsB = bufB + AT_VS_BOFF;

            // ---- S = Q K^T (log2 domain) ----
            float s[16][4];
#pragma unroll
            for (int nt = 0; nt < 16; nt++)
#pragma unroll
                for (int r = 0; r < 4; r++) s[nt][r] = 0.f;

#pragma unroll
            for (int c = 0; c < 8; c++) {
                uint32_t bf[16][2];
#pragma unroll
                for (int p = 0; p < 8; p++)
                    LDSM_X4(bf[2 * p][0], bf[2 * p][1], bf[2 * p + 1][0], bf[2 * p + 1][1],
                            KsB + (uint32_t)(p * 16 + brow) * KS_ROW_BYTES
                                + (uint32_t)c * 32 + bcol16);
#pragma unroll
                for (int nt = 0; nt < 16; nt++)
                    MMA_F16(s[nt], aQ[c], bf[nt]);
            }

            // ---- causal mask ----
            if (k0 + 127 > q0 + w * 16) {
#pragma unroll
                for (int nt = 0; nt < 16; nt++) {
                    int c0 = k0 + nt * 8 + 2 * lk;
                    if (c0     > row0g)     s[nt][0] = -CUDART_INF_F;
                    if (c0 + 1 > row0g)     s[nt][1] = -CUDART_INF_F;
                    if (c0     > row0g + 8) s[nt][2] = -CUDART_INF_F;
                    if (c0 + 1 > row0g + 8) s[nt][3] = -CUDART_INF_F;
                }
            }

            // ---- max + rescale (log2 domain) ----
            float mt0 = -CUDART_INF_F, mt1 = -CUDART_INF_F;
#pragma unroll
            for (int nt = 0; nt < 16; nt++) {
                mt0 = fmaxf(mt0, fmaxf(s[nt][0], s[nt][1]));
                mt1 = fmaxf(mt1, fmaxf(s[nt][2], s[nt][3]));
            }
#pragma unroll
            for (int off = 1; off <= 2; off <<= 1) {
                mt0 = fmaxf(mt0, __shfl_xor_sync(0xffffffffu, mt0, off));
                mt1 = fmaxf(mt1, __shfl_xor_sync(0xffffffffu, mt1, off));
            }
            float mn0 = fmaxf(m0, mt0), mn1 = fmaxf(m1, mt1);
            float al0 = exp2f(m0 - mn0), al1 = exp2f(m1 - mn1);
            m0 = mn0; m1 = mn1;
            l0 *= al0; l1 *= al1;
#pragma unroll
            for (int nt = 0; nt < 16; nt++) {
                O[nt][0] *= al0; O[nt][1] *= al0;
                O[nt][2] *= al1; O[nt][3] *= al1;
            }

            // ---- PV with on-the-fly f16x2 exp2; l via ones-MMA ----
            const half2 mh0 = __float2half2_rn(mn0);
            const half2 mh1 = __float2half2_rn(mn1);
            float lacc[4] = {0.f, 0.f, 0.f, 0.f};
            uint32_t ones[2] = { oneh2, oneh2 };
#pragma unroll
            for (int c = 0; c < 8; c++) {
                uint32_t pa[4];
                pa[0] = exp2_pair(s[2 * c][0],     s[2 * c][1],     mh0);
                pa[1] = exp2_pair(s[2 * c][2],     s[2 * c][3],     mh1);
                pa[2] = exp2_pair(s[2 * c + 1][0], s[2 * c + 1][1], mh0);
                pa[3] = exp2_pair(s[2 * c + 1][2], s[2 * c + 1][3], mh1);
                MMA_F16(lacc, pa, ones);
#pragma unroll
                for (int p = 0; p < 8; p++) {
                    uint32_t vb[2][2];
                    LDSM_X4_T(vb[0][0], vb[0][1], vb[1][0], vb[1][1],
                              VsB + (uint32_t)(c * 16 + arow) * KS_ROW_BYTES
                                  + (uint32_t)p * 32 + asel16);
                    MMA_F16(O[2 * p],     pa, vb[0]);
                    MMA_F16(O[2 * p + 1], pa, vb[1]);
                }
            }
            l0 += lacc[0];
            l1 += lacc[2];
        }

        if (kt + 1 < nkt) CP_WAIT0();
        __syncthreads();
    }

    // ---- epilogue (half out) ----
    float inv0 = 1.0f / l0, inv1 = 1.0f / l1;
    size_t r0base = (size_t)(b * T_ + q0 + w * 16 + lr) * D_ + h * HD_;
    size_t r1base = (size_t)(b * T_ + q0 + w * 16 + lr + 8) * D_ + h * HD_;
#pragma unroll
    for (int nt = 0; nt < 16; nt++) {
        *(uint32_t*)&o[r0base + nt * 8 + 2 * lk] = pk_h2(O[nt][0] * inv0, O[nt][1] * inv0);
        *(uint32_t*)&o[r1base + nt * 8 + 2 * lk] = pk_h2(O[nt][2] * inv1, O[nt][3] * inv1);
    }
}

// ---------------------------------------------------------------------------
// Launcher
// ---------------------------------------------------------------------------
extern "C" void kernel_launch(void* const* d_in, const int* in_sizes, int n_in,
                              void* d_out, int out_size)
{
    const float* x    = (const float*)d_in[0];
    const float* cosT = (const float*)d_in[1];
    const float* sinT = (const float*)d_in[2];
    const float* Wq   = (const float*)d_in[3];
    const float* Wk   = (const float*)d_in[4];
    const float* Wv   = (const float*)d_in[5];
    const float* Wo   = (const float*)d_in[6];
    float* out = (float*)d_out;

    __half *xh, *wqkvh, *woh, *gqkv, *gattn;
    cudaGetSymbolAddress((void**)&xh,    g_xh);
    cudaGetSymbolAddress((void**)&wqkvh, g_wqkvh);
    cudaGetSymbolAddress((void**)&woh,   g_woh);
    cudaGetSymbolAddress((void**)&gqkv,  g_qkv);
    cudaGetSymbolAddress((void**)&gattn, g_attn);

    cudaFuncSetAttribute(attn_f16_kernel, cudaFuncAttributeMaxDynamicSharedMemorySize,
                         ATTN_SMEM_BYTES);
    cudaFuncSetAttribute(gemm_nt_h_kernel,
                         cudaFuncAttributeMaxDynamicSharedMemorySize,
                         GEMM_SMEM_BYTES);

    dim3 blk(256);
    f2h_all_kernel<<<F2H_BLOCKS, blk>>>(x, Wq, Wk, Wv, Wo, xh, wqkvh, woh);

    dim3 qkv_grid(QKVN_ / 128, M_ / 128);   // 24 x 32 = 768 CTAs
    gemm_nt_h_kernel<<<qkv_grid, blk, GEMM_SMEM_BYTES>>>(xh, wqkvh, gqkv, nullptr,
                                                         M_, QKVN_, D_);

    rope_h_kernel<<<M_, blk>>>(gqkv, cosT, sinT);

    dim3 ga(T_ / 128, H_, B_);
    attn_f16_kernel<<<ga, blk, ATTN_SMEM_BYTES>>>(gqkv, gattn);

    dim3 go_grid(D_ / 128, M_ / 128);
    gemm_nt_h_kernel<<<go_grid, blk, GEMM_SMEM_BYTES>>>(gattn, woh, nullptr, out,
                                                        M_, D_, D_);
}